// round 4
// baseline (speedup 1.0000x reference)
#include <cuda_runtime.h>

#define DD 160
#define NN 82944
#define BB 4
#define NT 128
#define NBLK 648            /* NN / NT */
#define PAD 129
#define EPSV 1e-6f
#define NBLKF 162           /* NN / 512 for float4 final kernel */

// Scratch state (device globals: no allocation allowed)
__device__ float g_c[BB * NN];          // coef, 1.33 MB
__device__ float g_v[BB * DD];          // bases vector
__device__ float g_s[BB];               // ||v||^2
__device__ float g_wp[BB * NBLK * DD];  // per-block partials of w = X c  (1.66 MB)
__device__ float g_tp[BB * NBLK];       // per-block partials of t = ||c||^2

// ---------------------------------------------------------------------------
// init: v = bases, s = ||v||^2
// ---------------------------------------------------------------------------
__global__ void init_kernel(const float* __restrict__ bases) {
    int b = blockIdx.x, d = threadIdx.x;
    __shared__ float sh[DD];
    float v = bases[b * DD + d];
    g_v[b * DD + d] = v;
    sh[d] = v * v;
    __syncthreads();
    if (d == 0) {
        float s = 0.f;
        for (int i = 0; i < DD; i++) s += sh[i];
        g_s[b] = s;
    }
}

// ---------------------------------------------------------------------------
// One NMF step, fused: single DRAM pass over X per step.
// Block = 128 threads, owns a 160x128 tile of X staged in padded SMEM.
// Pass 1: u[n] = sum_d X[d,n] v[d] (stream X -> SMEM), c update, t-partial.
// Pass 2: w-partials from SMEM tile (warp-per-row, shuffle reduce).
// ---------------------------------------------------------------------------
__global__ void __launch_bounds__(NT, 2) step_kernel(const float* __restrict__ x,
                                                     int first) {
    __shared__ float v_sh[DD];
    __shared__ float c_sh[NT];
    __shared__ float red[4];
    extern __shared__ float tile[];  // DD * PAD floats = 80.6 KB

    int b = blockIdx.y, blk = blockIdx.x, tid = threadIdx.x;
    int lane = tid & 31, wid = tid >> 5;

    for (int i = tid; i < DD; i += NT) v_sh[i] = g_v[b * DD + i];
    __syncthreads();

    float s = g_s[b];
    const float* xb = x + (size_t)b * DD * NN + (size_t)blk * NT;

    float u = 0.f;
#pragma unroll 8
    for (int d = 0; d < DD; d++) {
        float xv = xb[(size_t)d * NN + tid];
        u = fmaf(xv, v_sh[d], u);
        tile[d * PAD + tid] = xv;
    }

    size_t cidx = (size_t)b * NN + (size_t)blk * NT + tid;
    float cold = first ? 1.f : g_c[cidx];
    float cn = cold * u / (cold * s + EPSV);
    g_c[cidx] = cn;
    c_sh[tid] = cn;

    // t-partial: block reduce cn^2
    float tv = cn * cn;
#pragma unroll
    for (int off = 16; off; off >>= 1) tv += __shfl_xor_sync(0xffffffffu, tv, off);
    if (lane == 0) red[wid] = tv;
    __syncthreads();
    if (tid == 0) g_tp[b * NBLK + blk] = red[0] + red[1] + red[2] + red[3];

    // Pass 2: w[d] partial = sum_{n in tile} tile[d][n] * cn[n]
    float* wp = g_wp + ((size_t)b * NBLK + blk) * DD;
    for (int d = wid; d < DD; d += 4) {
        const float* row = tile + d * PAD;
        float acc = 0.f;
#pragma unroll
        for (int m = 0; m < 4; m++) {
            int j = lane + 32 * m;
            acc = fmaf(row[j], c_sh[j], acc);
        }
#pragma unroll
        for (int off = 16; off; off >>= 1)
            acc += __shfl_xor_sync(0xffffffffu, acc, off);
        if (lane == 0) wp[d] = acc;
    }
}

// ---------------------------------------------------------------------------
// v update: reduce partials deterministically, v = v*w/(v*t+eps), s = ||v||^2
// Grid: 4 blocks (one per batch), 640 threads.
// ---------------------------------------------------------------------------
__global__ void vupdate_kernel() {
    __shared__ float shw[640];
    __shared__ float sht[DD];
    __shared__ float shs[DD];
    __shared__ float t_tot;
    int b = blockIdx.x, tid = threadIdx.x;
    int d = tid % DD, chunk = tid / DD;  // 4 chunks x 162 blocks each

    float wsum = 0.f;
    int k0 = chunk * 162;
    for (int k = k0; k < k0 + 162; k++)
        wsum += g_wp[((size_t)b * NBLK + k) * DD + d];
    shw[chunk * DD + d] = wsum;

    if (tid < DD) {
        float ts = 0.f;
        for (int k = tid; k < NBLK; k += DD) ts += g_tp[b * NBLK + k];
        sht[tid] = ts;
    }
    __syncthreads();
    if (tid == 0) {
        float t = 0.f;
        for (int i = 0; i < DD; i++) t += sht[i];
        t_tot = t;
    }
    __syncthreads();
    if (tid < DD) {
        float wfull = shw[tid] + shw[tid + DD] + shw[tid + 2 * DD] + shw[tid + 3 * DD];
        float vd = g_v[b * DD + tid];
        float vn = vd * wfull / (vd * t_tot + EPSV);
        g_v[b * DD + tid] = vn;
        shs[tid] = vn * vn;
    }
    __syncthreads();
    if (tid == 0) {
        float s = 0.f;
        for (int i = 0; i < DD; i++) s += shs[i];
        g_s[b] = s;
    }
}

// ---------------------------------------------------------------------------
// Final: u = X^T v, c' = c*u/(c*s+eps), out = v c'^T.  float4 over columns.
// ---------------------------------------------------------------------------
__global__ void __launch_bounds__(128) final_kernel(const float* __restrict__ x,
                                                    float* __restrict__ out) {
    __shared__ float v_sh[DD];
    int b = blockIdx.y, tid = threadIdx.x;
    size_t n0 = (size_t)blockIdx.x * 512 + (size_t)tid * 4;

    for (int i = tid; i < DD; i += 128) v_sh[i] = g_v[b * DD + i];
    __syncthreads();
    float s = g_s[b];

    const float* xb = x + (size_t)b * DD * NN + n0;
    float* ob = out + (size_t)b * DD * NN + n0;

    float4 u = make_float4(0.f, 0.f, 0.f, 0.f);
#pragma unroll 8
    for (int d = 0; d < DD; d++) {
        float4 xv = *reinterpret_cast<const float4*>(xb + (size_t)d * NN);
        float vd = v_sh[d];
        u.x = fmaf(xv.x, vd, u.x);
        u.y = fmaf(xv.y, vd, u.y);
        u.z = fmaf(xv.z, vd, u.z);
        u.w = fmaf(xv.w, vd, u.w);
    }

    float4 co = *reinterpret_cast<const float4*>(g_c + (size_t)b * NN + n0);
    float4 cn;
    cn.x = co.x * u.x / (co.x * s + EPSV);
    cn.y = co.y * u.y / (co.y * s + EPSV);
    cn.z = co.z * u.z / (co.z * s + EPSV);
    cn.w = co.w * u.w / (co.w * s + EPSV);

#pragma unroll 8
    for (int d = 0; d < DD; d++) {
        float vd = v_sh[d];
        float4 o = make_float4(vd * cn.x, vd * cn.y, vd * cn.z, vd * cn.w);
        *reinterpret_cast<float4*>(ob + (size_t)d * NN) = o;
    }
}

// ---------------------------------------------------------------------------
extern "C" void kernel_launch(void* const* d_in, const int* in_sizes, int n_in,
                              void* d_out, int out_size) {
    const float* x = (const float*)d_in[0];
    const float* bases = (const float*)d_in[1];
    float* out = (float*)d_out;

    cudaFuncSetAttribute(step_kernel, cudaFuncAttributeMaxDynamicSharedMemorySize,
                         DD * PAD * (int)sizeof(float));

    init_kernel<<<BB, DD>>>(bases);
    for (int s = 0; s < 4; s++) {
        step_kernel<<<dim3(NBLK, BB), NT, DD * PAD * sizeof(float)>>>(x, s == 0);
        vupdate_kernel<<<BB, 640>>>();
    }
    final_kernel<<<dim3(NBLKF, BB), 128>>>(x, out);
}

// round 6
// speedup vs baseline: 1.9942x; 1.9942x over previous
#include <cuda_runtime.h>
#include <cstdint>

#define DD 160
#define NN 82944
#define BB 4
#define NT 128
#define NBLK 648            /* NN / NT */
#define RS 128              /* tile row stride in floats (512B, 16B aligned) */
#define EPSV 1e-6f
#define NBLKF 162           /* NN / 512 for float2 final kernel (256 thr x 2) */

// Scratch state (device globals: no allocation allowed)
__device__ float g_c[BB * NN];          // coef
__device__ float g_v[BB * DD];          // bases vector
__device__ float g_s[BB];               // ||v||^2
__device__ float g_wp[BB * NBLK * DD];  // per-block partials of w = X c
__device__ float g_tp[BB * NBLK];       // per-block partials of t = ||c||^2

// ---------------------------------------------------------------------------
// cp.async helpers (LDGSTS on sm_103a)
// ---------------------------------------------------------------------------
__device__ __forceinline__ void cpasync16(uint32_t dst, const void* src) {
    asm volatile("cp.async.cg.shared.global [%0], [%1], 16;\n" :: "r"(dst), "l"(src));
}
__device__ __forceinline__ void cpcommit() {
    asm volatile("cp.async.commit_group;\n" ::: "memory");
}
template <int N>
__device__ __forceinline__ void cpwait() {
    asm volatile("cp.async.wait_group %0;\n" :: "n"(N) : "memory");
}

// ---------------------------------------------------------------------------
// init: v = bases, s = ||v||^2
// ---------------------------------------------------------------------------
__global__ void init_kernel(const float* __restrict__ bases) {
    int b = blockIdx.x, d = threadIdx.x;
    __shared__ float sh[DD];
    float v = bases[b * DD + d];
    g_v[b * DD + d] = v;
    sh[d] = v * v;
    __syncthreads();
    if (d == 0) {
        float s = 0.f;
        for (int i = 0; i < DD; i++) s += sh[i];
        g_s[b] = s;
    }
}

// ---------------------------------------------------------------------------
// One NMF step, fused: single DRAM pass over X per step.
// 128 threads own a 160x128 tile. All loads go through cp.async into SMEM
// (5 groups of 32 rows, issued up front -> deep DRAM pipeline, no register
// coupling). u is reduced from SMEM group-by-group behind wait_group.
// ---------------------------------------------------------------------------
__global__ void __launch_bounds__(NT, 2) step_kernel(const float* __restrict__ x,
                                                     int first) {
    __shared__ float v_sh[DD];
    __shared__ float c_sh[NT];
    __shared__ float red[4];
    extern __shared__ float tile[];  // DD * RS floats = 80 KB

    int b = blockIdx.y, blk = blockIdx.x, tid = threadIdx.x;
    int lane = tid & 31, wid = tid >> 5;

    const float* xb = x + (size_t)b * DD * NN + (size_t)blk * NT;
    uint32_t sbase = (uint32_t)__cvta_generic_to_shared(tile);

    // Fire all copies: group g covers rows [32g, 32g+32). Per inner iteration
    // the 128 threads move 4 rows (32 x 16B chunks per row). Thread's (row
    // offset, chunk) within each 4-row slab is fixed -> cheap addressing.
    {
        int drow = tid >> 5;           // 0..3 row-within-slab
        int ch4 = (tid & 31) * 4;      // float offset of this thread's 16B chunk
        const float* gsrc = xb + (size_t)drow * NN + ch4;
        uint32_t sdst = sbase + (uint32_t)(drow * RS + ch4) * 4u;
#pragma unroll
        for (int g = 0; g < 5; g++) {
#pragma unroll
            for (int it = 0; it < 8; it++) {
                int d4 = g * 32 + it * 4;  // slab base row
                cpasync16(sdst + (uint32_t)(d4 * RS) * 4u,
                          gsrc + (size_t)d4 * NN);
            }
            cpcommit();
        }
    }

    for (int i = tid; i < DD; i += NT) v_sh[i] = g_v[b * DD + i];
    float s = g_s[b];

    float u0 = 0.f, u1 = 0.f, u2 = 0.f, u3 = 0.f;

#define UGROUP(g)                                                   \
    do {                                                            \
        _Pragma("unroll")                                           \
        for (int d = (g)*32; d < (g)*32 + 32; d += 4) {             \
            u0 = fmaf(tile[(d + 0) * RS + tid], v_sh[d + 0], u0);   \
            u1 = fmaf(tile[(d + 1) * RS + tid], v_sh[d + 1], u1);   \
            u2 = fmaf(tile[(d + 2) * RS + tid], v_sh[d + 2], u2);   \
            u3 = fmaf(tile[(d + 3) * RS + tid], v_sh[d + 3], u3);   \
        }                                                           \
    } while (0)

    cpwait<4>(); __syncthreads(); UGROUP(0);
    cpwait<3>(); __syncthreads(); UGROUP(1);
    cpwait<2>(); __syncthreads(); UGROUP(2);
    cpwait<1>(); __syncthreads(); UGROUP(3);
    cpwait<0>(); __syncthreads(); UGROUP(4);
#undef UGROUP

    float u = (u0 + u1) + (u2 + u3);

    size_t cidx = (size_t)b * NN + (size_t)blk * NT + tid;
    float cold = first ? 1.f : g_c[cidx];
    float cn = cold * u / (cold * s + EPSV);
    g_c[cidx] = cn;
    c_sh[tid] = cn;

    // t-partial: block reduce cn^2
    float tv = cn * cn;
#pragma unroll
    for (int off = 16; off; off >>= 1) tv += __shfl_xor_sync(0xffffffffu, tv, off);
    if (lane == 0) red[wid] = tv;
    __syncthreads();
    if (tid == 0) g_tp[b * NBLK + blk] = red[0] + red[1] + red[2] + red[3];

    // Pass 2: w[d] partial = sum_{n in tile} tile[d][n] * cn[n]  (SMEM only)
    float* wp = g_wp + ((size_t)b * NBLK + blk) * DD;
    for (int d = wid; d < DD; d += 4) {
        const float* row = tile + d * RS;
        float acc = 0.f;
#pragma unroll
        for (int m = 0; m < 4; m++) {
            int j = lane + 32 * m;
            acc = fmaf(row[j], c_sh[j], acc);
        }
#pragma unroll
        for (int off = 16; off; off >>= 1)
            acc += __shfl_xor_sync(0xffffffffu, acc, off);
        if (lane == 0) wp[d] = acc;
    }
}

// ---------------------------------------------------------------------------
// v update: reduce partials deterministically, v = v*w/(v*t+eps), s = ||v||^2
// ---------------------------------------------------------------------------
__global__ void vupdate_kernel() {
    __shared__ float shw[640];
    __shared__ float sht[DD];
    __shared__ float shs[DD];
    __shared__ float t_tot;
    int b = blockIdx.x, tid = threadIdx.x;
    int d = tid % DD, chunk = tid / DD;  // 4 chunks x 162 blocks each

    float wsum = 0.f;
    int k0 = chunk * 162;
    for (int k = k0; k < k0 + 162; k++)
        wsum += g_wp[((size_t)b * NBLK + k) * DD + d];
    shw[chunk * DD + d] = wsum;

    if (tid < DD) {
        float ts = 0.f;
        for (int k = tid; k < NBLK; k += DD) ts += g_tp[b * NBLK + k];
        sht[tid] = ts;
    }
    __syncthreads();
    if (tid == 0) {
        float t = 0.f;
        for (int i = 0; i < DD; i++) t += sht[i];
        t_tot = t;
    }
    __syncthreads();
    if (tid < DD) {
        float wfull = shw[tid] + shw[tid + DD] + shw[tid + 2 * DD] + shw[tid + 3 * DD];
        float vd = g_v[b * DD + tid];
        float vn = vd * wfull / (vd * t_tot + EPSV);
        g_v[b * DD + tid] = vn;
        shs[tid] = vn * vn;
    }
    __syncthreads();
    if (tid == 0) {
        float s = 0.f;
        for (int i = 0; i < DD; i++) s += shs[i];
        g_s[b] = s;
    }
}

// ---------------------------------------------------------------------------
// Final: u = X^T v, c' = c*u/(c*s+eps), out = v c'^T.
// float2 per thread, 256-thread blocks -> ~1120 threads/SM.
// ---------------------------------------------------------------------------
__global__ void __launch_bounds__(256) final_kernel(const float* __restrict__ x,
                                                    float* __restrict__ out) {
    __shared__ float v_sh[DD];
    int b = blockIdx.y, tid = threadIdx.x;
    size_t n0 = (size_t)blockIdx.x * 512 + (size_t)tid * 2;

    for (int i = tid; i < DD; i += 256) v_sh[i] = g_v[b * DD + i];
    __syncthreads();
    float s = g_s[b];

    const float* xb = x + (size_t)b * DD * NN + n0;
    float* ob = out + (size_t)b * DD * NN + n0;

    float ux = 0.f, uy = 0.f;
#pragma unroll 8
    for (int d = 0; d < DD; d++) {
        float2 xv = *reinterpret_cast<const float2*>(xb + (size_t)d * NN);
        float vd = v_sh[d];
        ux = fmaf(xv.x, vd, ux);
        uy = fmaf(xv.y, vd, uy);
    }

    float2 co = *reinterpret_cast<const float2*>(g_c + (size_t)b * NN + n0);
    float cnx = co.x * ux / (co.x * s + EPSV);
    float cny = co.y * uy / (co.y * s + EPSV);

#pragma unroll 8
    for (int d = 0; d < DD; d++) {
        float vd = v_sh[d];
        float2 o = make_float2(vd * cnx, vd * cny);
        *reinterpret_cast<float2*>(ob + (size_t)d * NN) = o;
    }
}

// ---------------------------------------------------------------------------
extern "C" void kernel_launch(void* const* d_in, const int* in_sizes, int n_in,
                              void* d_out, int out_size) {
    const float* x = (const float*)d_in[0];
    const float* bases = (const float*)d_in[1];
    float* out = (float*)d_out;

    cudaFuncSetAttribute(step_kernel, cudaFuncAttributeMaxDynamicSharedMemorySize,
                         DD * RS * (int)sizeof(float));

    init_kernel<<<BB, DD>>>(bases);
    for (int s = 0; s < 4; s++) {
        step_kernel<<<dim3(NBLK, BB), NT, DD * RS * sizeof(float)>>>(x, s == 0);
        vupdate_kernel<<<BB, 640>>>();
    }
    final_kernel<<<dim3(NBLKF, BB), 256>>>(x, out);
}